// round 15
// baseline (speedup 1.0000x reference)
#include <cuda_runtime.h>
#include <cstdint>

#define NMAX   500000
#define HBITS  21
#define HSIZE  (1u << HBITS)
#define HMASK  (HSIZE - 1u)
#define EMPTYK 0xFFFFFFFFu
#define SP     40          // smem point-stride (floats): 32 points + 8 pad

typedef unsigned long long ull;
typedef unsigned int uint;

// ---------------- device scratch ----------------
__device__ uint32_t g_keys[3][HSIZE];
__device__ int      g_vals[3][HSIZE];
__device__ int      g_counter[3];
__device__ int      g_pt2vox[3][NMAX];
__device__ float    g_sums[3][NMAX * 64];
__device__ int      g_counts[3][NMAX];
__device__ float    g_inv[3][NMAX];
__device__ int      g_ptidx[3][NMAX];
__device__ float    g_ms[3][NMAX * 64];

__device__ __forceinline__ uint32_t hash32(uint32_t x) {
    x ^= x >> 16; x *= 0x85ebca6bu;
    x ^= x >> 13; x *= 0xc2b2ae35u;
    x ^= x >> 16;
    return x;
}

__device__ __forceinline__ uint f2tf(float v) {
    uint r;
    asm("cvt.rna.tf32.f32 %0, %1;" : "=r"(r) : "f"(v));
    return r;
}

// D += A(tf32) * B(tf32), m16n8k8, A row-major, B col-major, fp32 accum
__device__ __forceinline__ void mma_tf32(float4& d, const uint* a, uint b0, uint b1) {
    asm("mma.sync.aligned.m16n8k8.row.col.f32.tf32.tf32.f32 "
        "{%0,%1,%2,%3}, {%4,%5,%6,%7}, {%8,%9}, {%0,%1,%2,%3};"
        : "+f"(d.x), "+f"(d.y), "+f"(d.z), "+f"(d.w)
        : "r"(a[0]), "r"(a[1]), "r"(a[2]), "r"(a[3]), "r"(b0), "r"(b1));
}

// ---------------- K1: clear hash tables + counts ----------------
__global__ void k_clear(int n) {
    int tid = blockIdx.x * blockDim.x + threadIdx.x;
    int stride = gridDim.x * blockDim.x;
    for (int i = tid; i < (int)HSIZE; i += stride) {
        g_keys[0][i] = EMPTYK; g_keys[1][i] = EMPTYK; g_keys[2][i] = EMPTYK;
        g_vals[0][i] = -1;     g_vals[1][i] = -1;     g_vals[2][i] = -1;
    }
    for (int i = tid; i < n; i += stride) {
        g_counts[0][i] = 0; g_counts[1][i] = 0; g_counts[2][i] = 0;
    }
    if (tid == 0) { g_counter[0] = 0; g_counter[1] = 0; g_counter[2] = 0; }
}

// ---------------- K2: hash-insert; winner zeroes its voxel's sum row ----------------
__global__ void k_insert(const int* __restrict__ coords, int n) {
    int i = blockIdx.x * blockDim.x + threadIdx.x;
    if (i >= n) return;
    int si = blockIdx.y;
    int shift = si + 1;
    int4 cd = reinterpret_cast<const int4*>(coords)[i];
    int vx = cd.x >> shift, vy = cd.y >> shift, vz = cd.z >> shift;
    uint32_t key = (uint32_t)((((cd.w * 512) + vx) * 512 + vy) * 512 + vz);
    uint32_t slot = hash32(key) & HMASK;
    int id = -1;
#pragma unroll 1
    while (true) {
        uint32_t old = atomicCAS(&g_keys[si][slot], EMPTYK, key);
        if (old == EMPTYK) {
            id = atomicAdd(&g_counter[si], 1);
            // zero this voxel's feature-sum row (overlaps hash latency;
            // k_accum runs in a later kernel, so ordering is by launch)
            float4 z = make_float4(0.f, 0.f, 0.f, 0.f);
            float4* dst = reinterpret_cast<float4*>(&g_sums[si][(size_t)id * 64]);
#pragma unroll
            for (int q = 0; q < 16; q++) dst[q] = z;
            atomicExch(&g_vals[si][slot], id);
            break;
        }
        if (old == key) {
            volatile int* vp = (volatile int*)&g_vals[si][slot];
#pragma unroll 1
            while ((id = *vp) < 0) { __nanosleep(40); }
            break;
        }
        slot = (slot + 1) & HMASK;
    }
    g_pt2vox[si][i] = id;
    atomicAdd(&g_counts[si][id], 1);
}

// ---------------- K2b: per-voxel 1/count only ----------------
__global__ void k_inv() {
    int tid = blockIdx.x * blockDim.x + threadIdx.x;
    int stride = gridDim.x * blockDim.x;
#pragma unroll
    for (int s = 0; s < 3; s++) {
        int nv = g_counter[s];
        for (int i = tid; i < nv; i += stride)
            g_inv[s][i] = 1.0f / (float)g_counts[s][i];
    }
}

// ---------------- K3: per-voxel feature sums (all 3 scales, one feats read) ----------------
__global__ void k_accum(const float* __restrict__ feats, int n) {
    int tid = blockIdx.x * blockDim.x + threadIdx.x;
    if (tid >= n * 16) return;
    int p = tid >> 4, q = tid & 15;
    float4 v = reinterpret_cast<const float4*>(feats)[tid];
#pragma unroll
    for (int si = 0; si < 3; si++) {
        int vid = g_pt2vox[si][p];
        float* dst = &g_sums[si][(size_t)vid * 64 + q * 4];
        asm volatile("red.global.add.v4.f32 [%0], {%1, %2, %3, %4};"
                     :: "l"(dst), "f"(v.x), "f"(v.y), "f"(v.z), "f"(v.w)
                     : "memory");
    }
}

// ---------------- K4: 8-corner probe + exact trilinear argmax ----------------
__device__ __forceinline__ int hlookup(int si, uint32_t key) {
    uint32_t slot = hash32(key) & HMASK;
#pragma unroll 1
    while (true) {
        uint32_t k = g_keys[si][slot];
        if (k == key) return g_vals[si][slot];
        if (k == EMPTYK) return -1;
        slot = (slot + 1) & HMASK;
    }
}

__global__ void k_select(const int* __restrict__ coords, int n) {
    int i = blockIdx.x * blockDim.x + threadIdx.x;
    if (i >= n) return;
    int si = blockIdx.y;
    int shift = si + 1;
    int4 cd = reinterpret_cast<const int4*>(coords)[i];
    int scale = 1 << shift;
    float invs = 1.0f / (float)scale;
    int vx = cd.x >> shift, vy = cd.y >> shift, vz = cd.z >> shift;
    float fx = (float)(cd.x - (vx << shift)) * invs;   // exact binary fractions
    float fy = (float)(cd.y - (vy << shift)) * invs;
    float fz = (float)(cd.z - (vz << shift)) * invs;
    float gx = 1.0f - fx, gy = 1.0f - fy, gz = 1.0f - fz;

    float bestw = -1.0f;
    int bestid = 0;
#pragma unroll
    for (int j = 0; j < 8; j++) {
        int bx = (j >> 2) & 1, by = (j >> 1) & 1, bz = j & 1;
        float w = (bx ? fx : gx) * (by ? fy : gy) * (bz ? fz : gz);  // exact
        uint32_t key = (uint32_t)((((cd.w * 512) + (vx + bx)) * 512 + (vy + by)) * 512 + (vz + bz));
        int id = hlookup(si, key);
        float val = (id >= 0) ? w : 0.0f;
        if (val > bestw) { bestw = val; bestid = id; }  // first-max == jnp.argmax
    }
    g_ptidx[si][i] = bestid;
}

// ---------------- K5: per-scale residual MLP via tf32 tensor MMA (32-pt tiles) ----------------
// R11 structure: CTA = 128 thr = 4 warps; warp w owns output channels
// [16w,16w+16); weights as register A-fragments; activations transposed
// [chan][pt] stride SP=40; 32 points/tile; 5 CTAs/SM persistent.
// New: next tile's (idx, inv) prefetched during MMA phases, shortening the
// phase-0 dependent-load chain from 3 levels to 1.
__global__ __launch_bounds__(128, 5) void k_mlp(
    const float* __restrict__ feats,
    const float* __restrict__ W1g, const float* __restrict__ b1g,
    const float* __restrict__ W2g, const float* __restrict__ b2g,
    int n)
{
    __shared__ float resT[64 * SP];
    __shared__ float fT[64 * SP];
    __shared__ float hT[64 * SP];

    const int s  = blockIdx.y;
    const int w  = threadIdx.x >> 5;
    const int l  = threadIdx.x & 31;
    const int gr = l >> 2;     // group row 0..7
    const int tg = l & 3;      // thread-in-group 0..3

    // ---- load weight A-fragments (tf32) once ----
    uint a1f[8][4], a2f[8][4];
    const int m0 = 16 * w + gr;
#pragma unroll
    for (int kt = 0; kt < 8; kt++) {
        int kb = 8 * kt;
        a1f[kt][0] = f2tf(W1g[s * 4096 + (kb + tg) * 64 + m0]);
        a1f[kt][1] = f2tf(W1g[s * 4096 + (kb + tg) * 64 + m0 + 8]);
        a1f[kt][2] = f2tf(W1g[s * 4096 + (kb + tg + 4) * 64 + m0]);
        a1f[kt][3] = f2tf(W1g[s * 4096 + (kb + tg + 4) * 64 + m0 + 8]);
        a2f[kt][0] = f2tf(W2g[s * 4096 + (kb + tg) * 64 + m0]);
        a2f[kt][1] = f2tf(W2g[s * 4096 + (kb + tg) * 64 + m0 + 8]);
        a2f[kt][2] = f2tf(W2g[s * 4096 + (kb + tg + 4) * 64 + m0]);
        a2f[kt][3] = f2tf(W2g[s * 4096 + (kb + tg + 4) * 64 + m0 + 8]);
    }
    const float b1lo = b1g[s * 64 + m0], b1hi = b1g[s * 64 + m0 + 8];
    const float b2lo = b2g[s * 64 + m0], b2hi = b2g[s * 64 + m0 + 8];

    const int tiles = (n + 31) >> 5;
    const int pp = threadIdx.x & 31;      // this thread's point within a tile
    const int cg = threadIdx.x >> 5;      // channel group for gather

    // ---- prefetch first tile's (idx, inv) ----
    int pidx = 0; float pinv = 0.f;
    if (blockIdx.x < tiles) {
        int i = blockIdx.x * 32 + pp; if (i >= n) i = n - 1;
        pidx = g_ptidx[s][i];
        pinv = g_inv[s][pidx];
    }

    for (int t = blockIdx.x; t < tiles; t += gridDim.x) {
        const int i0 = t * 32;

        // ---- gather + transpose using prefetched (idx, inv) ----
        {
            int i = i0 + pp; if (i >= n) i = n - 1;
            const float4* fr = (const float4*)&feats[(size_t)i * 64 + cg * 16];
            const float4* sr = (const float4*)&g_sums[s][(size_t)pidx * 64 + cg * 16];
#pragma unroll
            for (int q = 0; q < 4; q++) {
                float4 f = fr[q];
                float4 sv = sr[q];
                int c = cg * 16 + q * 4;
                fT[(c + 0) * SP + pp] = f.x;  resT[(c + 0) * SP + pp] = f.x - sv.x * pinv;
                fT[(c + 1) * SP + pp] = f.y;  resT[(c + 1) * SP + pp] = f.y - sv.y * pinv;
                fT[(c + 2) * SP + pp] = f.z;  resT[(c + 2) * SP + pp] = f.z - sv.z * pinv;
                fT[(c + 3) * SP + pp] = f.w;  resT[(c + 3) * SP + pp] = f.w - sv.w * pinv;
            }
        }
        __syncthreads();

        // ---- layer 1: h = relu(W1^T @ res + b1) * feats ----
#pragma unroll
        for (int nt = 0; nt < 4; nt++) {
            float4 C = make_float4(0.f, 0.f, 0.f, 0.f);
            const int col = gr + nt * 8;
#pragma unroll
            for (int kt = 0; kt < 8; kt++) {
                uint b0 = f2tf(resT[(tg + kt * 8) * SP + col]);
                uint b1 = f2tf(resT[(tg + 4 + kt * 8) * SP + col]);
                mma_tf32(C, a1f[kt], b0, b1);
            }
            int pc = 2 * tg + nt * 8;
            float2 flo = *(const float2*)&fT[m0 * SP + pc];
            float2 fhi = *(const float2*)&fT[(m0 + 8) * SP + pc];
            float2 hlo, hhi;
            hlo.x = fmaxf(C.x + b1lo, 0.f) * flo.x;
            hlo.y = fmaxf(C.y + b1lo, 0.f) * flo.y;
            hhi.x = fmaxf(C.z + b1hi, 0.f) * fhi.x;
            hhi.y = fmaxf(C.w + b1hi, 0.f) * fhi.y;
            *(float2*)&hT[m0 * SP + pc] = hlo;
            *(float2*)&hT[(m0 + 8) * SP + pc] = hhi;
        }
        __syncthreads();

        // ---- prefetch next tile's (idx, inv): hidden behind layer-2 MMAs ----
        {
            int tn = t + gridDim.x;
            if (tn < tiles) {
                int i = tn * 32 + pp; if (i >= n) i = n - 1;
                pidx = g_ptidx[s][i];
                pinv = g_inv[s][pidx];
            }
        }

        // ---- layer 2: ms = relu(W2^T @ h + b2) -> g_ms ----
#pragma unroll
        for (int nt = 0; nt < 4; nt++) {
            float4 C = make_float4(0.f, 0.f, 0.f, 0.f);
            const int col = gr + nt * 8;
#pragma unroll
            for (int kt = 0; kt < 8; kt++) {
                uint b0 = f2tf(hT[(tg + kt * 8) * SP + col]);
                uint b1 = f2tf(hT[(tg + 4 + kt * 8) * SP + col]);
                mma_tf32(C, a2f[kt], b0, b1);
            }
            int p0 = i0 + 2 * tg + nt * 8;
            if (p0 < n) {
                g_ms[s][(size_t)p0 * 64 + m0]     = fmaxf(C.x + b2lo, 0.f);
                g_ms[s][(size_t)p0 * 64 + m0 + 8] = fmaxf(C.z + b2hi, 0.f);
            }
            if (p0 + 1 < n) {
                g_ms[s][(size_t)(p0 + 1) * 64 + m0]     = fmaxf(C.y + b2lo, 0.f);
                g_ms[s][(size_t)(p0 + 1) * 64 + m0 + 8] = fmaxf(C.w + b2hi, 0.f);
            }
        }
        __syncthreads();   // protect resT/fT/hT WAR for next tile
    }
}

// ---------------- K6: attention + combine (streaming) ----------------
__global__ __launch_bounds__(256) void k_att(
    const float* __restrict__ Wag, const float* __restrict__ bag,
    float* __restrict__ out, int n)
{
    int warp = threadIdx.x >> 5, lane = threadIdx.x & 31;
    int i = blockIdx.x * 8 + warp;
    if (i >= n) return;
    int c0 = lane * 2;

    float2 m0 = *(const float2*)&g_ms[0][(size_t)i * 64 + c0];
    float2 m1 = *(const float2*)&g_ms[1][(size_t)i * 64 + c0];
    float2 m2 = *(const float2*)&g_ms[2][(size_t)i * 64 + c0];
    float ssx = m0.x + m1.x + m2.x;
    float ssy = m0.y + m1.y + m2.y;

    float2 wa0 = *(const float2*)&Wag[c0];
    float2 wa1 = *(const float2*)&Wag[64 + c0];
    float2 wa2 = *(const float2*)&Wag[128 + c0];
    float p0 = ssx * wa0.x + ssy * wa0.y;
    float p1 = ssx * wa1.x + ssy * wa1.y;
    float p2 = ssx * wa2.x + ssy * wa2.y;
#pragma unroll
    for (int off = 16; off; off >>= 1) {
        p0 += __shfl_xor_sync(0xffffffffu, p0, off);
        p1 += __shfl_xor_sync(0xffffffffu, p1, off);
        p2 += __shfl_xor_sync(0xffffffffu, p2, off);
    }
    float a0 = 1.0f / (1.0f + expf(-(p0 + bag[0])));
    float a1 = 1.0f / (1.0f + expf(-(p1 + bag[1])));
    float a2 = 1.0f / (1.0f + expf(-(p2 + bag[2])));

    float2 o;
    o.x = m0.x * a0 + m1.x * a1 + m2.x * a2;
    o.y = m0.y * a0 + m1.y * a1 + m2.y * a2;
    *(float2*)&out[(size_t)i * 64 + c0] = o;
}

// ---------------- host launcher ----------------
extern "C" void kernel_launch(void* const* d_in, const int* in_sizes, int n_in,
                              void* d_out, int out_size) {
    const float* feats = (const float*)d_in[0];
    const int*   coords = (const int*)d_in[1];
    const float* W1 = (const float*)d_in[2];
    const float* b1 = (const float*)d_in[3];
    const float* W2 = (const float*)d_in[4];
    const float* b2 = (const float*)d_in[5];
    const float* Wa = (const float*)d_in[6];
    const float* ba = (const float*)d_in[7];
    float* out = (float*)d_out;

    int n = in_sizes[1] / 4;   // coords is (N,4) int32
    if (n > NMAX) n = NMAX;

    k_clear<<<2048, 256>>>(n);
    dim3 gi((n + 255) / 256, 3);
    k_insert<<<gi, 256>>>(coords, n);
    k_inv<<<1024, 256>>>();
    k_accum<<<(n * 16 + 255) / 256, 256>>>(feats, n);
    k_select<<<gi, 256>>>(coords, n);

    int sms = 148;
    cudaDeviceGetAttribute(&sms, cudaDevAttrMultiProcessorCount, 0);
    dim3 gm(sms * 5, 3);   // 5 CTAs/SM resident, persistent over tiles
    k_mlp<<<gm, 128>>>(feats, W1, b1, W2, b2, n);

    k_att<<<(n + 7) / 8, 256>>>(Wa, ba, out, n);
}

// round 16
// speedup vs baseline: 1.3377x; 1.3377x over previous
#include <cuda_runtime.h>
#include <cstdint>

#define NMAX   500000
#define HBITS  21
#define HSIZE  (1u << HBITS)
#define HMASK  (HSIZE - 1u)
#define EMPTYK 0xFFFFFFFFu
#define SP     40          // smem point-stride (floats): 32 points + 8 pad
#define TILESMAX ((NMAX + 31) / 32)

typedef unsigned long long ull;
typedef unsigned int uint;

// ---------------- device scratch ----------------
__device__ uint32_t g_keys[3][HSIZE];
__device__ int      g_vals[3][HSIZE];
__device__ int      g_counter[3];
__device__ int      g_pt2vox[3][NMAX];
__device__ float    g_sums[3][NMAX * 64];
__device__ int      g_counts[3][NMAX];
__device__ float    g_inv[3][NMAX];
__device__ int      g_ptidx[3][NMAX];
__device__ float    g_ms[3][NMAX * 64];
__device__ int      g_tilecnt[TILESMAX];

__device__ __forceinline__ uint32_t hash32(uint32_t x) {
    x ^= x >> 16; x *= 0x85ebca6bu;
    x ^= x >> 13; x *= 0xc2b2ae35u;
    x ^= x >> 16;
    return x;
}

__device__ __forceinline__ uint f2tf(float v) {
    uint r;
    asm("cvt.rna.tf32.f32 %0, %1;" : "=r"(r) : "f"(v));
    return r;
}

// D += A(tf32) * B(tf32), m16n8k8, A row-major, B col-major, fp32 accum
__device__ __forceinline__ void mma_tf32(float4& d, const uint* a, uint b0, uint b1) {
    asm("mma.sync.aligned.m16n8k8.row.col.f32.tf32.tf32.f32 "
        "{%0,%1,%2,%3}, {%4,%5,%6,%7}, {%8,%9}, {%0,%1,%2,%3};"
        : "+f"(d.x), "+f"(d.y), "+f"(d.z), "+f"(d.w)
        : "r"(a[0]), "r"(a[1]), "r"(a[2]), "r"(a[3]), "r"(b0), "r"(b1));
}

// ---------------- K1: clear hash tables + counts + tile counters ----------------
__global__ void k_clear(int n) {
    int tid = blockIdx.x * blockDim.x + threadIdx.x;
    int stride = gridDim.x * blockDim.x;
    for (int i = tid; i < (int)HSIZE; i += stride) {
        g_keys[0][i] = EMPTYK; g_keys[1][i] = EMPTYK; g_keys[2][i] = EMPTYK;
        g_vals[0][i] = -1;     g_vals[1][i] = -1;     g_vals[2][i] = -1;
    }
    for (int i = tid; i < n; i += stride) {
        g_counts[0][i] = 0; g_counts[1][i] = 0; g_counts[2][i] = 0;
    }
    for (int i = tid; i < TILESMAX; i += stride) g_tilecnt[i] = 0;
    if (tid == 0) { g_counter[0] = 0; g_counter[1] = 0; g_counter[2] = 0; }
}

// ---------------- K2: hash-insert (all scales via blockIdx.y) ----------------
__global__ void k_insert(const int* __restrict__ coords, int n) {
    int i = blockIdx.x * blockDim.x + threadIdx.x;
    if (i >= n) return;
    int si = blockIdx.y;
    int shift = si + 1;
    int4 cd = reinterpret_cast<const int4*>(coords)[i];
    int vx = cd.x >> shift, vy = cd.y >> shift, vz = cd.z >> shift;
    uint32_t key = (uint32_t)((((cd.w * 512) + vx) * 512 + vy) * 512 + vz);
    uint32_t slot = hash32(key) & HMASK;
    int id = -1;
#pragma unroll 1
    while (true) {
        uint32_t old = atomicCAS(&g_keys[si][slot], EMPTYK, key);
        if (old == EMPTYK) {
            id = atomicAdd(&g_counter[si], 1);
            atomicExch(&g_vals[si][slot], id);
            break;
        }
        if (old == key) {
            volatile int* vp = (volatile int*)&g_vals[si][slot];
#pragma unroll 1
            while ((id = *vp) < 0) { __nanosleep(40); }
            break;
        }
        slot = (slot + 1) & HMASK;
    }
    g_pt2vox[si][i] = id;
    atomicAdd(&g_counts[si][id], 1);
}

// ---------------- K2b: zero live prefix of sums + per-voxel 1/count ----------------
__global__ void k_post() {
    int tid = blockIdx.x * blockDim.x + threadIdx.x;
    int stride = gridDim.x * blockDim.x;
    float4 z = make_float4(0.f, 0.f, 0.f, 0.f);
#pragma unroll
    for (int s = 0; s < 3; s++) {
        int nv = g_counter[s];
        float4* s4 = reinterpret_cast<float4*>(&g_sums[s][0]);
        int m4 = nv * 16;
        for (int i = tid; i < m4; i += stride) s4[i] = z;
        for (int i = tid; i < nv; i += stride)
            g_inv[s][i] = 1.0f / (float)g_counts[s][i];
    }
}

// ---------------- K3: per-voxel feature sums (all 3 scales, one feats read) ----------------
__global__ void k_accum(const float* __restrict__ feats, int n) {
    int tid = blockIdx.x * blockDim.x + threadIdx.x;
    if (tid >= n * 16) return;
    int p = tid >> 4, q = tid & 15;
    float4 v = reinterpret_cast<const float4*>(feats)[tid];
#pragma unroll
    for (int si = 0; si < 3; si++) {
        int vid = g_pt2vox[si][p];
        float* dst = &g_sums[si][(size_t)vid * 64 + q * 4];
        asm volatile("red.global.add.v4.f32 [%0], {%1, %2, %3, %4};"
                     :: "l"(dst), "f"(v.x), "f"(v.y), "f"(v.z), "f"(v.w)
                     : "memory");
    }
}

// ---------------- K4: 7-corner probe (corner 000 = own voxel, known) ----------------
__device__ __forceinline__ int hlookup(int si, uint32_t key) {
    uint32_t slot = hash32(key) & HMASK;
#pragma unroll 1
    while (true) {
        uint32_t k = g_keys[si][slot];
        if (k == key) return g_vals[si][slot];
        if (k == EMPTYK) return -1;
        slot = (slot + 1) & HMASK;
    }
}

__global__ void k_select(const int* __restrict__ coords, int n) {
    int i = blockIdx.x * blockDim.x + threadIdx.x;
    if (i >= n) return;
    int si = blockIdx.y;
    int shift = si + 1;
    int4 cd = reinterpret_cast<const int4*>(coords)[i];
    int scale = 1 << shift;
    float invs = 1.0f / (float)scale;
    int vx = cd.x >> shift, vy = cd.y >> shift, vz = cd.z >> shift;
    float fx = (float)(cd.x - (vx << shift)) * invs;   // exact binary fractions
    float fy = (float)(cd.y - (vy << shift)) * invs;
    float fz = (float)(cd.z - (vz << shift)) * invs;
    float gx = 1.0f - fx, gy = 1.0f - fy, gz = 1.0f - fz;

    // corner (0,0,0) is the point's own voxel: always present, id known.
    float bestw = gx * gy * gz;
    int bestid = g_pt2vox[si][i];
#pragma unroll
    for (int j = 1; j < 8; j++) {
        int bx = (j >> 2) & 1, by = (j >> 1) & 1, bz = j & 1;
        float w = (bx ? fx : gx) * (by ? fy : gy) * (bz ? fz : gz);  // exact
        uint32_t key = (uint32_t)((((cd.w * 512) + (vx + bx)) * 512 + (vy + by)) * 512 + (vz + bz));
        int id = hlookup(si, key);
        float val = (id >= 0) ? w : 0.0f;
        if (val > bestw) { bestw = val; bestid = id; }  // first-max == jnp.argmax
    }
    g_ptidx[si][i] = bestid;
}

// ---------------- K5: per-scale tf32 MLP + last-finisher attention epilogue ----------------
// R11 hot structure: CTA = 128 thr = 4 warps; warp w owns output channels
// [16w,16w+16); weights as register A-fragments; activations transposed
// [chan][pt] stride SP=40; 32 points/tile; 5 CTAs/SM persistent.
// New: after writing g_ms for tile t, CTAs bump g_tilecnt[t]; the CTA that
// brings it to 3 runs attention + blend inline (g_ms lines still L2-hot).
__global__ __launch_bounds__(128, 5) void k_mlp(
    const float* __restrict__ feats,
    const float* __restrict__ W1g, const float* __restrict__ b1g,
    const float* __restrict__ W2g, const float* __restrict__ b2g,
    const float* __restrict__ Wag, const float* __restrict__ bag,
    float* __restrict__ out, int n)
{
    __shared__ float resT[64 * SP];
    __shared__ float fT[64 * SP];
    __shared__ float hT[64 * SP];
    __shared__ int sflag;

    const int s  = blockIdx.y;
    const int w  = threadIdx.x >> 5;
    const int l  = threadIdx.x & 31;
    const int gr = l >> 2;     // group row 0..7
    const int tg = l & 3;      // thread-in-group 0..3

    // ---- load weight A-fragments (tf32) once ----
    uint a1f[8][4], a2f[8][4];
    const int m0 = 16 * w + gr;
#pragma unroll
    for (int kt = 0; kt < 8; kt++) {
        int kb = 8 * kt;
        a1f[kt][0] = f2tf(W1g[s * 4096 + (kb + tg) * 64 + m0]);
        a1f[kt][1] = f2tf(W1g[s * 4096 + (kb + tg) * 64 + m0 + 8]);
        a1f[kt][2] = f2tf(W1g[s * 4096 + (kb + tg + 4) * 64 + m0]);
        a1f[kt][3] = f2tf(W1g[s * 4096 + (kb + tg + 4) * 64 + m0 + 8]);
        a2f[kt][0] = f2tf(W2g[s * 4096 + (kb + tg) * 64 + m0]);
        a2f[kt][1] = f2tf(W2g[s * 4096 + (kb + tg) * 64 + m0 + 8]);
        a2f[kt][2] = f2tf(W2g[s * 4096 + (kb + tg + 4) * 64 + m0]);
        a2f[kt][3] = f2tf(W2g[s * 4096 + (kb + tg + 4) * 64 + m0 + 8]);
    }
    const float b1lo = b1g[s * 64 + m0], b1hi = b1g[s * 64 + m0 + 8];
    const float b2lo = b2g[s * 64 + m0], b2hi = b2g[s * 64 + m0 + 8];

    const int tiles = (n + 31) >> 5;

    for (int t = blockIdx.x; t < tiles; t += gridDim.x) {
        const int i0 = t * 32;

        // ---- gather + transpose: res and feats into [chan][pt] smem ----
        {
            int p  = threadIdx.x & 31;
            int cg = threadIdx.x >> 5;           // 0..3
            int i = i0 + p; if (i >= n) i = n - 1;
            int idx = g_ptidx[s][i];
            float inv = g_inv[s][idx];
            const float4* fr = (const float4*)&feats[(size_t)i * 64 + cg * 16];
            const float4* sr = (const float4*)&g_sums[s][(size_t)idx * 64 + cg * 16];
#pragma unroll
            for (int q = 0; q < 4; q++) {
                float4 f = fr[q];
                float4 sv = sr[q];
                int c = cg * 16 + q * 4;
                fT[(c + 0) * SP + p] = f.x;  resT[(c + 0) * SP + p] = f.x - sv.x * inv;
                fT[(c + 1) * SP + p] = f.y;  resT[(c + 1) * SP + p] = f.y - sv.y * inv;
                fT[(c + 2) * SP + p] = f.z;  resT[(c + 2) * SP + p] = f.z - sv.z * inv;
                fT[(c + 3) * SP + p] = f.w;  resT[(c + 3) * SP + p] = f.w - sv.w * inv;
            }
        }
        __syncthreads();

        // ---- layer 1: h = relu(W1^T @ res + b1) * feats ----
#pragma unroll
        for (int nt = 0; nt < 4; nt++) {
            float4 C = make_float4(0.f, 0.f, 0.f, 0.f);
            const int col = gr + nt * 8;
#pragma unroll
            for (int kt = 0; kt < 8; kt++) {
                uint b0 = f2tf(resT[(tg + kt * 8) * SP + col]);
                uint b1 = f2tf(resT[(tg + 4 + kt * 8) * SP + col]);
                mma_tf32(C, a1f[kt], b0, b1);
            }
            int pc = 2 * tg + nt * 8;
            float2 flo = *(const float2*)&fT[m0 * SP + pc];
            float2 fhi = *(const float2*)&fT[(m0 + 8) * SP + pc];
            float2 hlo, hhi;
            hlo.x = fmaxf(C.x + b1lo, 0.f) * flo.x;
            hlo.y = fmaxf(C.y + b1lo, 0.f) * flo.y;
            hhi.x = fmaxf(C.z + b1hi, 0.f) * fhi.x;
            hhi.y = fmaxf(C.w + b1hi, 0.f) * fhi.y;
            *(float2*)&hT[m0 * SP + pc] = hlo;
            *(float2*)&hT[(m0 + 8) * SP + pc] = hhi;
        }
        __syncthreads();

        // ---- layer 2: ms = relu(W2^T @ h + b2) -> g_ms ----
#pragma unroll
        for (int nt = 0; nt < 4; nt++) {
            float4 C = make_float4(0.f, 0.f, 0.f, 0.f);
            const int col = gr + nt * 8;
#pragma unroll
            for (int kt = 0; kt < 8; kt++) {
                uint b0 = f2tf(hT[(tg + kt * 8) * SP + col]);
                uint b1 = f2tf(hT[(tg + 4 + kt * 8) * SP + col]);
                mma_tf32(C, a2f[kt], b0, b1);
            }
            int p0 = i0 + 2 * tg + nt * 8;
            if (p0 < n) {
                g_ms[s][(size_t)p0 * 64 + m0]     = fmaxf(C.x + b2lo, 0.f);
                g_ms[s][(size_t)p0 * 64 + m0 + 8] = fmaxf(C.z + b2hi, 0.f);
            }
            if (p0 + 1 < n) {
                g_ms[s][(size_t)(p0 + 1) * 64 + m0]     = fmaxf(C.y + b2lo, 0.f);
                g_ms[s][(size_t)(p0 + 1) * 64 + m0 + 8] = fmaxf(C.w + b2hi, 0.f);
            }
        }

        // ---- tile-completion: last of the 3 scale-CTAs does attention+blend ----
        __threadfence();
        __syncthreads();   // all ms writes issued+fenced; also WAR for smem
        if (threadIdx.x == 0)
            sflag = (atomicAdd(&g_tilecnt[t], 1) == 2) ? 1 : 0;
        __syncthreads();

        if (sflag) {
            int c0 = 2 * l;
            float2 wa0 = *(const float2*)&Wag[c0];
            float2 wa1 = *(const float2*)&Wag[64 + c0];
            float2 wa2 = *(const float2*)&Wag[128 + c0];
            float ba0 = bag[0], ba1 = bag[1], ba2 = bag[2];
#pragma unroll 1
            for (int rep = 0; rep < 8; rep++) {
                int i = i0 + w * 8 + rep;
                if (i < n) {
                    float2 m0v = *(const float2*)&g_ms[0][(size_t)i * 64 + c0];
                    float2 m1v = *(const float2*)&g_ms[1][(size_t)i * 64 + c0];
                    float2 m2v = *(const float2*)&g_ms[2][(size_t)i * 64 + c0];
                    float ssx = m0v.x + m1v.x + m2v.x;
                    float ssy = m0v.y + m1v.y + m2v.y;
                    float p0 = ssx * wa0.x + ssy * wa0.y;
                    float p1 = ssx * wa1.x + ssy * wa1.y;
                    float p2 = ssx * wa2.x + ssy * wa2.y;
#pragma unroll
                    for (int off = 16; off; off >>= 1) {
                        p0 += __shfl_xor_sync(0xffffffffu, p0, off);
                        p1 += __shfl_xor_sync(0xffffffffu, p1, off);
                        p2 += __shfl_xor_sync(0xffffffffu, p2, off);
                    }
                    float a0 = 1.0f / (1.0f + expf(-(p0 + ba0)));
                    float a1 = 1.0f / (1.0f + expf(-(p1 + ba1)));
                    float a2 = 1.0f / (1.0f + expf(-(p2 + ba2)));
                    float2 o;
                    o.x = m0v.x * a0 + m1v.x * a1 + m2v.x * a2;
                    o.y = m0v.y * a0 + m1v.y * a1 + m2v.y * a2;
                    *(float2*)&out[(size_t)i * 64 + c0] = o;
                }
            }
        }
    }
}

// ---------------- host launcher ----------------
extern "C" void kernel_launch(void* const* d_in, const int* in_sizes, int n_in,
                              void* d_out, int out_size) {
    const float* feats = (const float*)d_in[0];
    const int*   coords = (const int*)d_in[1];
    const float* W1 = (const float*)d_in[2];
    const float* b1 = (const float*)d_in[3];
    const float* W2 = (const float*)d_in[4];
    const float* b2 = (const float*)d_in[5];
    const float* Wa = (const float*)d_in[6];
    const float* ba = (const float*)d_in[7];
    float* out = (float*)d_out;

    int n = in_sizes[1] / 4;   // coords is (N,4) int32
    if (n > NMAX) n = NMAX;

    k_clear<<<2048, 256>>>(n);
    dim3 gi((n + 255) / 256, 3);
    k_insert<<<gi, 256>>>(coords, n);
    k_post<<<2048, 256>>>();
    k_accum<<<(n * 16 + 255) / 256, 256>>>(feats, n);
    k_select<<<gi, 256>>>(coords, n);

    int sms = 148;
    cudaDeviceGetAttribute(&sms, cudaDevAttrMultiProcessorCount, 0);
    dim3 gm(sms * 5, 3);   // 5 CTAs/SM resident, persistent over tiles
    k_mlp<<<gm, 128>>>(feats, W1, b1, W2, b2, Wa, ba, out, n);
}

// round 17
// speedup vs baseline: 1.5558x; 1.1630x over previous
#include <cuda_runtime.h>
#include <cstdint>

#define NMAX   500000
#define HBITS  21
#define HSIZE  (1u << HBITS)
#define HMASK  (HSIZE - 1u)
#define EMPTYK 0xFFFFFFFFu
#define SP     40          // smem point-stride (floats): 32 points + 8 pad

typedef unsigned long long ull;
typedef unsigned int uint;

// ---------------- device scratch ----------------
__device__ uint32_t g_keys[3][HSIZE];
__device__ int      g_vals[3][HSIZE];
__device__ int      g_counter[3];
__device__ int      g_pt2vox[3][NMAX];
__device__ float    g_sums[3][NMAX * 64];
__device__ int      g_counts[3][NMAX];
__device__ float    g_inv[3][NMAX];
__device__ int      g_ptidx[3][NMAX];
__device__ float    g_ms[3][NMAX * 64];

__device__ __forceinline__ uint32_t hash32(uint32_t x) {
    x ^= x >> 16; x *= 0x85ebca6bu;
    x ^= x >> 13; x *= 0xc2b2ae35u;
    x ^= x >> 16;
    return x;
}

__device__ __forceinline__ uint f2tf(float v) {
    uint r;
    asm("cvt.rna.tf32.f32 %0, %1;" : "=r"(r) : "f"(v));
    return r;
}

// D += A(tf32) * B(tf32), m16n8k8, A row-major, B col-major, fp32 accum
__device__ __forceinline__ void mma_tf32(float4& d, const uint* a, uint b0, uint b1) {
    asm("mma.sync.aligned.m16n8k8.row.col.f32.tf32.tf32.f32 "
        "{%0,%1,%2,%3}, {%4,%5,%6,%7}, {%8,%9}, {%0,%1,%2,%3};"
        : "+f"(d.x), "+f"(d.y), "+f"(d.z), "+f"(d.w)
        : "r"(a[0]), "r"(a[1]), "r"(a[2]), "r"(a[3]), "r"(b0), "r"(b1));
}

// ---------------- K1: clear hash tables + counts ----------------
__global__ void k_clear(int n) {
    int tid = blockIdx.x * blockDim.x + threadIdx.x;
    int stride = gridDim.x * blockDim.x;
    for (int i = tid; i < (int)HSIZE; i += stride) {
        g_keys[0][i] = EMPTYK; g_keys[1][i] = EMPTYK; g_keys[2][i] = EMPTYK;
        g_vals[0][i] = -1;     g_vals[1][i] = -1;     g_vals[2][i] = -1;
    }
    for (int i = tid; i < n; i += stride) {
        g_counts[0][i] = 0; g_counts[1][i] = 0; g_counts[2][i] = 0;
    }
    if (tid == 0) { g_counter[0] = 0; g_counter[1] = 0; g_counter[2] = 0; }
}

// ---------------- K2: hash-insert (all scales via blockIdx.y) ----------------
__global__ void k_insert(const int* __restrict__ coords, int n) {
    int i = blockIdx.x * blockDim.x + threadIdx.x;
    if (i >= n) return;
    int si = blockIdx.y;
    int shift = si + 1;
    int4 cd = reinterpret_cast<const int4*>(coords)[i];
    int vx = cd.x >> shift, vy = cd.y >> shift, vz = cd.z >> shift;
    uint32_t key = (uint32_t)((((cd.w * 512) + vx) * 512 + vy) * 512 + vz);
    uint32_t slot = hash32(key) & HMASK;
    int id = -1;
#pragma unroll 1
    while (true) {
        uint32_t old = atomicCAS(&g_keys[si][slot], EMPTYK, key);
        if (old == EMPTYK) {
            id = atomicAdd(&g_counter[si], 1);
            atomicExch(&g_vals[si][slot], id);
            break;
        }
        if (old == key) {
            volatile int* vp = (volatile int*)&g_vals[si][slot];
#pragma unroll 1
            while ((id = *vp) < 0) { __nanosleep(40); }
            break;
        }
        slot = (slot + 1) & HMASK;
    }
    g_pt2vox[si][i] = id;
    atomicAdd(&g_counts[si][id], 1);
}

// ---------------- K2b: zero live prefix of sums + per-voxel 1/count ----------------
__global__ void k_post() {
    int tid = blockIdx.x * blockDim.x + threadIdx.x;
    int stride = gridDim.x * blockDim.x;
    float4 z = make_float4(0.f, 0.f, 0.f, 0.f);
#pragma unroll
    for (int s = 0; s < 3; s++) {
        int nv = g_counter[s];
        float4* s4 = reinterpret_cast<float4*>(&g_sums[s][0]);
        int m4 = nv * 16;
        for (int i = tid; i < m4; i += stride) s4[i] = z;
        for (int i = tid; i < nv; i += stride)
            g_inv[s][i] = 1.0f / (float)g_counts[s][i];
    }
}

// ---------------- K3+K4 fused: select duty (latency-bound) + accum duty (DRAM-bound)
// co-resident in one launch so select's hash-probe latency hides inside
// accum's bandwidth stalls. First 3*nsel blocks: 7-corner argmax select.
// Remaining blocks: per-voxel feature-sum reductions.
__device__ __forceinline__ int hlookup(int si, uint32_t key) {
    uint32_t slot = hash32(key) & HMASK;
#pragma unroll 1
    while (true) {
        uint32_t k = g_keys[si][slot];
        if (k == key) return g_vals[si][slot];
        if (k == EMPTYK) return -1;
        slot = (slot + 1) & HMASK;
    }
}

__global__ void k_accsel(const float* __restrict__ feats,
                         const int* __restrict__ coords, int n, int nsel) {
    int b = blockIdx.x;
    if (b < 3 * nsel) {
        // ---- select duty: 7-corner probe + exact trilinear argmax ----
        int si = b / nsel;
        int i = (b - si * nsel) * 256 + threadIdx.x;
        if (i >= n) return;
        int shift = si + 1;
        int4 cd = reinterpret_cast<const int4*>(coords)[i];
        int scale = 1 << shift;
        float invs = 1.0f / (float)scale;
        int vx = cd.x >> shift, vy = cd.y >> shift, vz = cd.z >> shift;
        float fx = (float)(cd.x - (vx << shift)) * invs;   // exact binary fractions
        float fy = (float)(cd.y - (vy << shift)) * invs;
        float fz = (float)(cd.z - (vz << shift)) * invs;
        float gx = 1.0f - fx, gy = 1.0f - fy, gz = 1.0f - fz;

        // corner (0,0,0) is the point's own voxel: always present, id known.
        float bestw = gx * gy * gz;
        int bestid = g_pt2vox[si][i];
#pragma unroll
        for (int j = 1; j < 8; j++) {
            int bx = (j >> 2) & 1, by = (j >> 1) & 1, bz = j & 1;
            float w = (bx ? fx : gx) * (by ? fy : gy) * (bz ? fz : gz);  // exact
            uint32_t key = (uint32_t)((((cd.w * 512) + (vx + bx)) * 512 + (vy + by)) * 512 + (vz + bz));
            int id = hlookup(si, key);
            float val = (id >= 0) ? w : 0.0f;
            if (val > bestw) { bestw = val; bestid = id; }  // first-max == jnp.argmax
        }
        g_ptidx[si][i] = bestid;
    } else {
        // ---- accum duty: per-voxel feature sums (all 3 scales, one feats read) ----
        int tid = (b - 3 * nsel) * 256 + threadIdx.x;
        if (tid >= n * 16) return;
        int p = tid >> 4, q = tid & 15;
        float4 v = reinterpret_cast<const float4*>(feats)[tid];
#pragma unroll
        for (int si = 0; si < 3; si++) {
            int vid = g_pt2vox[si][p];
            float* dst = &g_sums[si][(size_t)vid * 64 + q * 4];
            asm volatile("red.global.add.v4.f32 [%0], {%1, %2, %3, %4};"
                         :: "l"(dst), "f"(v.x), "f"(v.y), "f"(v.z), "f"(v.w)
                         : "memory");
        }
    }
}

// ---------------- K5: per-scale residual MLP via tf32 tensor MMA (32-pt tiles) ----------------
// R11 EXACT: CTA = 128 thr = 4 warps; warp w owns output channels [16w,16w+16).
// Weights live in registers as A-fragments (loaded once, tf32).
// Activations transposed [chan][pt] in smem, stride SP=40, conflict-free
// B-frag LDS. 32 points per tile, 5 CTAs/SM persistent.
__global__ __launch_bounds__(128, 5) void k_mlp(
    const float* __restrict__ feats,
    const float* __restrict__ W1g, const float* __restrict__ b1g,
    const float* __restrict__ W2g, const float* __restrict__ b2g,
    int n)
{
    __shared__ float resT[64 * SP];
    __shared__ float fT[64 * SP];
    __shared__ float hT[64 * SP];

    const int s  = blockIdx.y;
    const int w  = threadIdx.x >> 5;
    const int l  = threadIdx.x & 31;
    const int gr = l >> 2;     // group row 0..7
    const int tg = l & 3;      // thread-in-group 0..3

    // ---- load weight A-fragments (tf32) once ----
    uint a1f[8][4], a2f[8][4];
    const int m0 = 16 * w + gr;
#pragma unroll
    for (int kt = 0; kt < 8; kt++) {
        int kb = 8 * kt;
        a1f[kt][0] = f2tf(W1g[s * 4096 + (kb + tg) * 64 + m0]);
        a1f[kt][1] = f2tf(W1g[s * 4096 + (kb + tg) * 64 + m0 + 8]);
        a1f[kt][2] = f2tf(W1g[s * 4096 + (kb + tg + 4) * 64 + m0]);
        a1f[kt][3] = f2tf(W1g[s * 4096 + (kb + tg + 4) * 64 + m0 + 8]);
        a2f[kt][0] = f2tf(W2g[s * 4096 + (kb + tg) * 64 + m0]);
        a2f[kt][1] = f2tf(W2g[s * 4096 + (kb + tg) * 64 + m0 + 8]);
        a2f[kt][2] = f2tf(W2g[s * 4096 + (kb + tg + 4) * 64 + m0]);
        a2f[kt][3] = f2tf(W2g[s * 4096 + (kb + tg + 4) * 64 + m0 + 8]);
    }
    const float b1lo = b1g[s * 64 + m0], b1hi = b1g[s * 64 + m0 + 8];
    const float b2lo = b2g[s * 64 + m0], b2hi = b2g[s * 64 + m0 + 8];

    const int tiles = (n + 31) >> 5;

    for (int t = blockIdx.x; t < tiles; t += gridDim.x) {
        const int i0 = t * 32;

        // ---- gather + transpose: res and feats into [chan][pt] smem ----
        {
            int p  = threadIdx.x & 31;
            int cg = threadIdx.x >> 5;           // 0..3
            int i = i0 + p; if (i >= n) i = n - 1;
            int idx = g_ptidx[s][i];
            float inv = g_inv[s][idx];
            const float4* fr = (const float4*)&feats[(size_t)i * 64 + cg * 16];
            const float4* sr = (const float4*)&g_sums[s][(size_t)idx * 64 + cg * 16];
#pragma unroll
            for (int q = 0; q < 4; q++) {
                float4 f = fr[q];
                float4 sv = sr[q];
                int c = cg * 16 + q * 4;
                fT[(c + 0) * SP + p] = f.x;  resT[(c + 0) * SP + p] = f.x - sv.x * inv;
                fT[(c + 1) * SP + p] = f.y;  resT[(c + 1) * SP + p] = f.y - sv.y * inv;
                fT[(c + 2) * SP + p] = f.z;  resT[(c + 2) * SP + p] = f.z - sv.z * inv;
                fT[(c + 3) * SP + p] = f.w;  resT[(c + 3) * SP + p] = f.w - sv.w * inv;
            }
        }
        __syncthreads();

        // ---- layer 1: h = relu(W1^T @ res + b1) * feats ----
#pragma unroll
        for (int nt = 0; nt < 4; nt++) {
            float4 C = make_float4(0.f, 0.f, 0.f, 0.f);
            const int col = gr + nt * 8;
#pragma unroll
            for (int kt = 0; kt < 8; kt++) {
                uint b0 = f2tf(resT[(tg + kt * 8) * SP + col]);
                uint b1 = f2tf(resT[(tg + 4 + kt * 8) * SP + col]);
                mma_tf32(C, a1f[kt], b0, b1);
            }
            int pc = 2 * tg + nt * 8;
            float2 flo = *(const float2*)&fT[m0 * SP + pc];
            float2 fhi = *(const float2*)&fT[(m0 + 8) * SP + pc];
            float2 hlo, hhi;
            hlo.x = fmaxf(C.x + b1lo, 0.f) * flo.x;
            hlo.y = fmaxf(C.y + b1lo, 0.f) * flo.y;
            hhi.x = fmaxf(C.z + b1hi, 0.f) * fhi.x;
            hhi.y = fmaxf(C.w + b1hi, 0.f) * fhi.y;
            *(float2*)&hT[m0 * SP + pc] = hlo;
            *(float2*)&hT[(m0 + 8) * SP + pc] = hhi;
        }
        __syncthreads();

        // ---- layer 2: ms = relu(W2^T @ h + b2) -> g_ms ----
#pragma unroll
        for (int nt = 0; nt < 4; nt++) {
            float4 C = make_float4(0.f, 0.f, 0.f, 0.f);
            const int col = gr + nt * 8;
#pragma unroll
            for (int kt = 0; kt < 8; kt++) {
                uint b0 = f2tf(hT[(tg + kt * 8) * SP + col]);
                uint b1 = f2tf(hT[(tg + 4 + kt * 8) * SP + col]);
                mma_tf32(C, a2f[kt], b0, b1);
            }
            int p0 = i0 + 2 * tg + nt * 8;
            if (p0 < n) {
                g_ms[s][(size_t)p0 * 64 + m0]     = fmaxf(C.x + b2lo, 0.f);
                g_ms[s][(size_t)p0 * 64 + m0 + 8] = fmaxf(C.z + b2hi, 0.f);
            }
            if (p0 + 1 < n) {
                g_ms[s][(size_t)(p0 + 1) * 64 + m0]     = fmaxf(C.y + b2lo, 0.f);
                g_ms[s][(size_t)(p0 + 1) * 64 + m0 + 8] = fmaxf(C.w + b2hi, 0.f);
            }
        }
        __syncthreads();   // protect resT/fT/hT WAR for next tile
    }
}

// ---------------- K6: attention + combine (streaming) ----------------
__global__ __launch_bounds__(256) void k_att(
    const float* __restrict__ Wag, const float* __restrict__ bag,
    float* __restrict__ out, int n)
{
    int warp = threadIdx.x >> 5, lane = threadIdx.x & 31;
    int i = blockIdx.x * 8 + warp;
    if (i >= n) return;
    int c0 = lane * 2;

    float2 m0 = *(const float2*)&g_ms[0][(size_t)i * 64 + c0];
    float2 m1 = *(const float2*)&g_ms[1][(size_t)i * 64 + c0];
    float2 m2 = *(const float2*)&g_ms[2][(size_t)i * 64 + c0];
    float ssx = m0.x + m1.x + m2.x;
    float ssy = m0.y + m1.y + m2.y;

    float2 wa0 = *(const float2*)&Wag[c0];
    float2 wa1 = *(const float2*)&Wag[64 + c0];
    float2 wa2 = *(const float2*)&Wag[128 + c0];
    float p0 = ssx * wa0.x + ssy * wa0.y;
    float p1 = ssx * wa1.x + ssy * wa1.y;
    float p2 = ssx * wa2.x + ssy * wa2.y;
#pragma unroll
    for (int off = 16; off; off >>= 1) {
        p0 += __shfl_xor_sync(0xffffffffu, p0, off);
        p1 += __shfl_xor_sync(0xffffffffu, p1, off);
        p2 += __shfl_xor_sync(0xffffffffu, p2, off);
    }
    float a0 = 1.0f / (1.0f + expf(-(p0 + bag[0])));
    float a1 = 1.0f / (1.0f + expf(-(p1 + bag[1])));
    float a2 = 1.0f / (1.0f + expf(-(p2 + bag[2])));

    float2 o;
    o.x = m0.x * a0 + m1.x * a1 + m2.x * a2;
    o.y = m0.y * a0 + m1.y * a1 + m2.y * a2;
    *(float2*)&out[(size_t)i * 64 + c0] = o;
}

// ---------------- host launcher ----------------
extern "C" void kernel_launch(void* const* d_in, const int* in_sizes, int n_in,
                              void* d_out, int out_size) {
    const float* feats = (const float*)d_in[0];
    const int*   coords = (const int*)d_in[1];
    const float* W1 = (const float*)d_in[2];
    const float* b1 = (const float*)d_in[3];
    const float* W2 = (const float*)d_in[4];
    const float* b2 = (const float*)d_in[5];
    const float* Wa = (const float*)d_in[6];
    const float* ba = (const float*)d_in[7];
    float* out = (float*)d_out;

    int n = in_sizes[1] / 4;   // coords is (N,4) int32
    if (n > NMAX) n = NMAX;

    k_clear<<<2048, 256>>>(n);
    dim3 gi((n + 255) / 256, 3);
    k_insert<<<gi, 256>>>(coords, n);
    k_post<<<2048, 256>>>();

    // fused select (latency-bound) + accum (DRAM-bound), co-resident
    int nsel = (n + 255) / 256;
    int nacc = (n * 16 + 255) / 256;
    k_accsel<<<3 * nsel + nacc, 256>>>(feats, coords, n, nsel);

    int sms = 148;
    cudaDeviceGetAttribute(&sms, cudaDevAttrMultiProcessorCount, 0);
    dim3 gm(sms * 5, 3);   // 5 CTAs/SM resident, persistent over tiles
    k_mlp<<<gm, 128>>>(feats, W1, b1, W2, b2, n);

    k_att<<<(n + 7) / 8, 256>>>(Wa, ba, out, n);
}